// round 4
// baseline (speedup 1.0000x reference)
#include <cuda_runtime.h>
#include <cstdint>

// ---------------- configuration ----------------
#define TOK_TILE     128
#define NUM_TILES    128          // 16384 / 128
#define THREADS      256          // 8 warps: 2 m-groups x 4 n-groups
#define KB_STEPS     8            // K=256 in blocks of 32
#define NCHUNKS      64           // 64 output chunks of 64 cols
#define NSLICES      (KB_STEPS * NCHUNKS)   // 512
#define SLICE_FLOATS 2048         // 64 o x 32 k
#define NBUF         4

// smem layout (bytes)
#define OFF_B        0
#define OFF_X2       (NBUF * SLICE_FLOATS * 4)          // 32768
#define X2_STRIDE    68
#define OFF_BIAS     (OFF_X2 + 128 * X2_STRIDE * 4)     // 32768 + 34816 = 67584
#define SMEM_BYTES   (OFF_BIAS + 4096 * 4)              // 83968

// W pre-transformed into per-(kb,c) fragment-ordered tf32 slices
__device__ float g_Wprep[4096 * 256];

static __device__ __forceinline__ uint32_t f2tf(float x) {
    uint32_t r; asm("cvt.rna.tf32.f32 %0, %1;" : "=r"(r) : "f"(x)); return r;
}
static __device__ __forceinline__ uint32_t smem_u32(const void* p) {
    uint32_t a;
    asm("{ .reg .u64 t; cvta.to.shared.u64 t, %1; cvt.u32.u64 %0, t; }" : "=r"(a) : "l"(p));
    return a;
}
// d = a*b + c   (fresh accumulator, c supplied: used for zero/bias init)
static __device__ __forceinline__ void mma_init(float& d0, float& d1, float& d2, float& d3,
                                                const uint32_t* a, uint32_t b0, uint32_t b1,
                                                float c0, float c1, float c2, float c3) {
    asm("mma.sync.aligned.m16n8k8.row.col.f32.tf32.tf32.f32 "
        "{%0,%1,%2,%3}, {%4,%5,%6,%7}, {%8,%9}, {%10,%11,%12,%13};"
        : "=f"(d0), "=f"(d1), "=f"(d2), "=f"(d3)
        : "r"(a[0]), "r"(a[1]), "r"(a[2]), "r"(a[3]), "r"(b0), "r"(b1),
          "f"(c0), "f"(c1), "f"(c2), "f"(c3));
}
// d += a*b
static __device__ __forceinline__ void mma_acc(float& d0, float& d1, float& d2, float& d3,
                                               const uint32_t* a, uint32_t b0, uint32_t b1) {
    asm("mma.sync.aligned.m16n8k8.row.col.f32.tf32.tf32.f32 "
        "{%0,%1,%2,%3}, {%4,%5,%6,%7}, {%8,%9}, {%0,%1,%2,%3};"
        : "+f"(d0), "+f"(d1), "+f"(d2), "+f"(d3)
        : "r"(a[0]), "r"(a[1]), "r"(a[2]), "r"(a[3]), "r"(b0), "r"(b1));
}

static __device__ __forceinline__ void issue_slice(uint32_t sb, int tid, int s) {
    if (s < NSLICES) {
        const float* src = g_Wprep + (size_t)s * SLICE_FLOATS + tid * 4;
        uint32_t dst = sb + (uint32_t)(((s & (NBUF - 1)) * SLICE_FLOATS + tid * 4) * 4);
        asm volatile("cp.async.cg.shared.global [%0], [%1], 16;" :: "r"(dst), "l"(src) : "memory");
        asm volatile("cp.async.cg.shared.global [%0], [%1], 16;"
                     :: "r"(dst + THREADS * 16), "l"(src + THREADS * 4) : "memory");
    }
    asm volatile("cp.async.commit_group;" ::: "memory");
}

// -------- W pre-transform: cvt.rna.tf32 + fragment-ordered layout --------
// dst slice (kb,c): z[g*512 + o*8 + r*2 + h] = tf32(W[c*64+o][kb*32 + g*8 + h*4 + r])
__global__ void prep_kernel(const float* __restrict__ W) {
    int idx = blockIdx.x * 256 + threadIdx.x;          // 1,048,576 threads
    uint32_t t = f2tf(W[idx]);
    int row = idx >> 8, k = idx & 255;
    int c = row >> 6, o = row & 63;
    int kb = k >> 5, kl = k & 31;
    int g = kl >> 3, w8 = kl & 7, h = w8 >> 2, r = w8 & 3;
    int dst = ((kb << 6) + c) * SLICE_FLOATS + (g << 9) + (o << 3) + (r << 1) + h;
    reinterpret_cast<uint32_t*>(g_Wprep)[dst] = t;
}

// -------- inner chunk body --------
template <bool FIRST>
static __device__ __forceinline__ void chunk_body(
    const uint32_t* __restrict__ Bb, const float* __restrict__ x2s,
    const float* __restrict__ bias_s, const uint32_t A[4][4][4],
    float y[4][2][4], int c, int rm, int cn, int gID, int tig)
{
    float xv[4][2];
#pragma unroll
    for (int mt = 0; mt < 4; mt++) {
        xv[mt][0] = x2s[(rm + mt * 16 + gID) * X2_STRIDE + c];
        xv[mt][1] = x2s[(rm + mt * 16 + gID + 8) * X2_STRIDE + c];
    }
#pragma unroll
    for (int nt = 0; nt < 2; nt++) {
        const int o_loc = cn + nt * 8 + gID;
        uint32_t b[4][2];
#pragma unroll
        for (int ks = 0; ks < 4; ks++) {
            uint2 v = *reinterpret_cast<const uint2*>(Bb + ks * 512 + o_loc * 8 + tig * 2);
            b[ks][0] = v.x; b[ks][1] = v.y;
        }
        float cq0 = 0.0f, cq1 = 0.0f;
        if (FIRST) {
            float2 bb = *reinterpret_cast<const float2*>(
                bias_s + c * 64 + cn + nt * 8 + tig * 2);
            cq0 = bb.x; cq1 = bb.y;
        }
#pragma unroll
        for (int mt = 0; mt < 4; mt++) {
            float d0, d1, d2, d3;
            mma_init(d0, d1, d2, d3, A[mt][0], b[0][0], b[0][1], cq0, cq1, cq0, cq1);
            mma_acc (d0, d1, d2, d3, A[mt][1], b[1][0], b[1][1]);
            mma_acc (d0, d1, d2, d3, A[mt][2], b[2][0], b[2][1]);
            mma_acc (d0, d1, d2, d3, A[mt][3], b[3][0], b[3][1]);
            y[mt][nt][0] = fmaf(xv[mt][0], d0, y[mt][nt][0]);
            y[mt][nt][1] = fmaf(xv[mt][0], d1, y[mt][nt][1]);
            y[mt][nt][2] = fmaf(xv[mt][1], d2, y[mt][nt][2]);
            y[mt][nt][3] = fmaf(xv[mt][1], d3, y[mt][nt][3]);
        }
    }
}

__global__ void __launch_bounds__(THREADS, 1)
metaLinear_kernel(const float* __restrict__ x1, const float* __restrict__ x2,
                  const float* __restrict__ bvec, float* __restrict__ out)
{
    extern __shared__ char smem[];
    float* Bs     = reinterpret_cast<float*>(smem + OFF_B);
    float* x2s    = reinterpret_cast<float*>(smem + OFF_X2);
    float* bias_s = reinterpret_cast<float*>(smem + OFF_BIAS);
    const uint32_t sb = smem_u32(smem);

    const int tid  = threadIdx.x;
    const int lane = tid & 31, wid = tid >> 5;
    const int wm = wid >> 2, wn = wid & 3;
    const int gID = lane >> 2, tig = lane & 3;
    const int tok0 = blockIdx.x * TOK_TILE;
    const int rm = wm * 64;
    const int cn = wn * 16;

    // stage x2 tile (padded stride 68) and bias into smem
    for (int i = tid; i < 128 * 64; i += THREADS) {
        int r = i >> 6, c = i & 63;
        x2s[r * X2_STRIDE + c] = x2[(size_t)(tok0 + r) * 64 + c];
    }
    for (int i = tid; i < 4096; i += THREADS) bias_s[i] = bvec[i];

    // prologue: prefetch 3 slices
    issue_slice(sb, tid, 0);
    issue_slice(sb, tid, 1);
    issue_slice(sb, tid, 2);

    uint32_t A[4][4][4];       // [m-tile][k-step][frag]
    float y[4][2][4];          // [m-tile][n-tile][frag]
#pragma unroll
    for (int mt = 0; mt < 4; mt++)
#pragma unroll
        for (int nt = 0; nt < 2; nt++)
#pragma unroll
            for (int j = 0; j < 4; j++) y[mt][nt][j] = 0.0f;

    int gslice = 0;
    for (int kb = 0; kb < KB_STEPS; kb++) {
        // load this k-block's A fragments into registers (kept across all 64 chunks)
        const float* a_base = x1 + (size_t)tok0 * 256 + kb * 32;
#pragma unroll
        for (int mt = 0; mt < 4; mt++) {
            const float* ar0 = a_base + (size_t)(rm + mt * 16 + gID) * 256;
            const float* ar1 = ar0 + 8 * 256;
#pragma unroll
            for (int ks = 0; ks < 4; ks++) {
                A[mt][ks][0] = f2tf(__ldg(ar0 + ks * 8 + tig));
                A[mt][ks][1] = f2tf(__ldg(ar1 + ks * 8 + tig));
                A[mt][ks][2] = f2tf(__ldg(ar0 + ks * 8 + tig + 4));
                A[mt][ks][3] = f2tf(__ldg(ar1 + ks * 8 + tig + 4));
            }
        }
        if (kb == 0) {
            for (int c = 0; c < NCHUNKS; c++) {
                asm volatile("cp.async.wait_group 2;" ::: "memory");
                __syncthreads();
                issue_slice(sb, tid, gslice + 3);
                const uint32_t* Bb = reinterpret_cast<const uint32_t*>(
                    Bs + (gslice & (NBUF - 1)) * SLICE_FLOATS);
                chunk_body<true>(Bb, x2s, bias_s, A, y, c, rm, cn, gID, tig);
                gslice++;
            }
        } else {
            for (int c = 0; c < NCHUNKS; c++) {
                asm volatile("cp.async.wait_group 2;" ::: "memory");
                __syncthreads();
                issue_slice(sb, tid, gslice + 3);
                const uint32_t* Bb = reinterpret_cast<const uint32_t*>(
                    Bs + (gslice & (NBUF - 1)) * SLICE_FLOATS);
                chunk_body<false>(Bb, x2s, bias_s, A, y, c, rm, cn, gID, tig);
                gslice++;
            }
        }
    }

    // write y
#pragma unroll
    for (int mt = 0; mt < 4; mt++)
#pragma unroll
        for (int h = 0; h < 2; h++) {
            int row = tok0 + rm + mt * 16 + gID + h * 8;
#pragma unroll
            for (int nt = 0; nt < 2; nt++) {
                float2 v;
                v.x = y[mt][nt][h * 2 + 0];
                v.y = y[mt][nt][h * 2 + 1];
                *reinterpret_cast<float2*>(
                    out + (size_t)row * 64 + cn + nt * 8 + tig * 2) = v;
            }
        }
}

extern "C" void kernel_launch(void* const* d_in, const int* in_sizes, int n_in,
                              void* d_out, int out_size) {
    const float* x1   = (const float*)d_in[0];
    const float* x2   = (const float*)d_in[1];
    const float* W    = (const float*)d_in[2];
    const float* bvec = (const float*)d_in[3];
    float* out = (float*)d_out;
    (void)in_sizes; (void)n_in; (void)out_size;

    prep_kernel<<<4096, 256>>>(W);

    static bool attr_set = false;
    cudaFuncSetAttribute(metaLinear_kernel,
                         cudaFuncAttributeMaxDynamicSharedMemorySize, SMEM_BYTES);
    (void)attr_set;
    metaLinear_kernel<<<NUM_TILES, THREADS, SMEM_BYTES>>>(x1, x2, bvec, out);
}